// round 15
// baseline (speedup 1.0000x reference)
#include <cuda_runtime.h>
#include <cuda_fp16.h>
#include <mma.h>
using namespace nvcuda;

#define N_NODES   100000
#define N_EDGES   1280000
#define D         64
#define N_GRAPHS  512
#define SCAN_B    1024
#define N_SCANBLK ((N_NODES + SCAN_B - 1) / SCAN_B)   // 98
#define LDW       72

// ---------------- scratch (device globals; no cudaMalloc allowed) -----------
__device__ __half g_h  [N_NODES * D];   // GEMM output, pre-scaled by dinv[row]
__device__ __half g_t0 [N_NODES * D];
__device__ __half g_t1 [N_NODES * D];
__device__ float  g_dinv[N_NODES];
__device__ int    g_dege[N_NODES + 1]; // [N_NODES] = last-block counter
__device__ int    g_rowstart[N_NODES + 1];
__device__ int    g_bsums[128];
__device__ int    g_csrc [N_EDGES];
__device__ int    g_rank [N_EDGES];
__device__ float  g_nodedot[N_NODES];

// ---------------- setup kernels ---------------------------------------------
__global__ void k_deg(const int* __restrict__ ei) {
    int t = blockIdx.x * blockDim.x + threadIdx.x;
    if (t < N_EDGES / 4) {
        int4 d4 = ((const int4*)(ei + N_EDGES))[t];
        int4 r;
        r.x = atomicAdd(&g_dege[d4.x], 1);
        r.y = atomicAdd(&g_dege[d4.y], 1);
        r.z = atomicAdd(&g_dege[d4.z], 1);
        r.w = atomicAdd(&g_dege[d4.w], 1);
        ((int4*)g_rank)[t] = r;
    }
}

// dinv only needs degrees -> runs right after k_deg so GEMM1 can fork early
__global__ void k_dinv() {
    int i = blockIdx.x * blockDim.x + threadIdx.x;
    if (i < N_NODES)
        g_dinv[i] = rsqrtf((float)(g_dege[i] + 1));   // +1 self loop
}

// per-tile scan + last-block scans the tile sums
__global__ void __launch_bounds__(1024) k_scan1() {
    __shared__ int sh[SCAN_B];
    __shared__ bool amLast;
    int tid = threadIdx.x;
    int i = blockIdx.x * SCAN_B + tid;
    int v = (i < N_NODES) ? g_dege[i] : 0;
    sh[tid] = v;
    __syncthreads();
    for (int off = 1; off < SCAN_B; off <<= 1) {
        int t = 0;
        if (tid >= off) t = sh[tid - off];
        __syncthreads();
        sh[tid] += t;
        __syncthreads();
    }
    int incl = sh[tid];
    if (i < N_NODES) g_rowstart[i] = incl - v;   // exclusive within tile
    if (tid == SCAN_B - 1) g_bsums[blockIdx.x] = incl;

    __threadfence();
    if (tid == 0) {
        int prev = atomicAdd(&g_dege[N_NODES], 1);
        amLast = (prev == (int)gridDim.x - 1);
    }
    __syncthreads();
    if (amLast) {
        int v2 = (tid < N_SCANBLK) ? g_bsums[tid] : 0;
        if (tid < 128) sh[tid] = v2;
        __syncthreads();
        for (int off = 1; off < 128; off <<= 1) {
            int t = (tid >= off && tid < 128) ? sh[tid - off] : 0;
            __syncthreads();
            if (tid < 128) sh[tid] += t;
            __syncthreads();
        }
        if (tid < N_SCANBLK) g_bsums[tid] = sh[tid] - v2;   // exclusive
        if (tid == N_SCANBLK - 1) g_rowstart[N_NODES] = sh[tid];
    }
}

__global__ void k_scan3() {
    int i = blockIdx.x * blockDim.x + threadIdx.x;
    if (i < N_NODES)
        g_rowstart[i] = g_rowstart[i] + g_bsums[i / SCAN_B];
}

__global__ void k_fill(const int* __restrict__ ei) {
    int t = blockIdx.x * blockDim.x + threadIdx.x;
    if (t < N_EDGES / 4) {
        int4 s4 = ((const int4*)ei)[t];
        int4 d4 = ((const int4*)(ei + N_EDGES))[t];
        int4 r4 = ((const int4*)g_rank)[t];
        g_csrc[g_rowstart[d4.x] + r4.x] = s4.x;
        g_csrc[g_rowstart[d4.y] + r4.y] = s4.y;
        g_csrc[g_rowstart[d4.z] + r4.z] = s4.z;
        g_csrc[g_rowstart[d4.w] + r4.w] = s4.w;
    }
}

// ---------------- tensor-core GEMM: out[row] = dinv[row]*(in[row] @ W), fp16 out
__device__ __forceinline__ void gemm_epilogue128(const float* osh, __half* __restrict__ out,
                                                 int blockRow0, int tid) {
    int r = tid >> 1;                 // 0..127
    int cbase = (tid & 1) * 32;
    int row = blockRow0 + r;
    if (row >= N_NODES) return;
    float s = g_dinv[row];
    uint4* orow = (uint4*)(out + (size_t)row * D + cbase);
    const float* src = osh + r * LDW + cbase;
#pragma unroll
    for (int q = 0; q < 4; q++) {
        __half2 p0 = __floats2half2_rn(src[q * 8 + 0] * s, src[q * 8 + 1] * s);
        __half2 p1 = __floats2half2_rn(src[q * 8 + 2] * s, src[q * 8 + 3] * s);
        __half2 p2 = __floats2half2_rn(src[q * 8 + 4] * s, src[q * 8 + 5] * s);
        __half2 p3 = __floats2half2_rn(src[q * 8 + 6] * s, src[q * 8 + 7] * s);
        uint4 u;
        u.x = *(unsigned*)&p0; u.y = *(unsigned*)&p1;
        u.z = *(unsigned*)&p2; u.w = *(unsigned*)&p3;
        orow[q] = u;
    }
}

__global__ void __launch_bounds__(256) k_gemm_f16(const __half* __restrict__ in,
                                                  const float* __restrict__ W,
                                                  __half* __restrict__ out) {
    __shared__ __half wsh[D * LDW];
    __shared__ float  osh[128 * LDW];
    int tid = threadIdx.x;
    for (int i = tid; i < D * D; i += 256) {
        int r = i >> 6, c = i & 63;
        wsh[r * LDW + c] = __float2half(W[i]);
    }
    __syncthreads();

    int warp = tid >> 5;
    int row0 = blockIdx.x * 128 + warp * 16;
    if (row0 < N_NODES) {
        wmma::fragment<wmma::accumulator, 16, 16, 16, float> acc[4];
#pragma unroll
        for (int n = 0; n < 4; n++) wmma::fill_fragment(acc[n], 0.0f);
#pragma unroll
        for (int k = 0; k < 4; k++) {
            wmma::fragment<wmma::matrix_a, 16, 16, 16, __half, wmma::row_major> a;
            wmma::load_matrix_sync(a, in + (size_t)row0 * D + k * 16, D);
#pragma unroll
            for (int n = 0; n < 4; n++) {
                wmma::fragment<wmma::matrix_b, 16, 16, 16, __half, wmma::row_major> b;
                wmma::load_matrix_sync(b, wsh + (k * 16) * LDW + n * 16, LDW);
                wmma::mma_sync(acc[n], a, b, acc[n]);
            }
        }
#pragma unroll
        for (int n = 0; n < 4; n++)
            wmma::store_matrix_sync(osh + (warp * 16) * LDW + n * 16, acc[n], LDW, wmma::mem_row_major);
    }
    __syncthreads();
    gemm_epilogue128(osh, out, blockIdx.x * 128, tid);
}

// fp32-input GEMM (layer 1): 256 threads / 128 rows; fp16 staging OVERLAYED
// on the fp32 output buffer (accumulators bridge the switch).
__global__ void __launch_bounds__(256) k_gemm_f32(const float* __restrict__ in,
                                                  const float* __restrict__ W,
                                                  __half* __restrict__ out) {
    __shared__ __half wsh[D * LDW];
    __shared__ float  osh[128 * LDW];
    __half* ash = (__half*)osh;
    int tid = threadIdx.x;

    for (int i = tid; i < D * D; i += 256) {
        int r = i >> 6, c = i & 63;
        wsh[r * LDW + c] = __float2half(W[i]);
    }
    for (int i = tid; i < 128 * D; i += 256) {
        int r = i >> 6, c = i & 63;
        int row = blockIdx.x * 128 + r;
        float v = (row < N_NODES) ? in[(size_t)row * D + c] : 0.f;
        ash[r * LDW + c] = __float2half(v);
    }
    __syncthreads();

    int warp = tid >> 5;
    int row0 = blockIdx.x * 128 + warp * 16;
    wmma::fragment<wmma::accumulator, 16, 16, 16, float> acc[4];
    if (row0 < N_NODES) {
#pragma unroll
        for (int n = 0; n < 4; n++) wmma::fill_fragment(acc[n], 0.0f);
#pragma unroll
        for (int k = 0; k < 4; k++) {
            wmma::fragment<wmma::matrix_a, 16, 16, 16, __half, wmma::row_major> a;
            wmma::load_matrix_sync(a, ash + (warp * 16) * LDW + k * 16, LDW);
#pragma unroll
            for (int n = 0; n < 4; n++) {
                wmma::fragment<wmma::matrix_b, 16, 16, 16, __half, wmma::row_major> b;
                wmma::load_matrix_sync(b, wsh + (k * 16) * LDW + n * 16, LDW);
                wmma::mma_sync(acc[n], a, b, acc[n]);
            }
        }
    }
    __syncthreads();   // all warps done reading ash before osh overwrites it
    if (row0 < N_NODES) {
#pragma unroll
        for (int n = 0; n < 4; n++)
            wmma::store_matrix_sync(osh + (warp * 16) * LDW + n * 16, acc[n], LDW, wmma::mem_row_major);
    }
    __syncthreads();
    gemm_epilogue128(osh, out, blockIdx.x * 128, tid);
}

// ------- gather: 8 lanes/node, LDG.128 per edge, half2-tree accumulate -------
template <bool FUSE_POOL>
__global__ void __launch_bounds__(256) k_gather8(const __half* __restrict__ h,
                                                 const float* __restrict__ b,
                                                 __half* __restrict__ out,
                                                 const float* __restrict__ fcw) {
    int gt = blockIdx.x * blockDim.x + threadIdx.x;
    int node = gt >> 3;
    int c = gt & 7;

    const float4* h4 = (const float4*)h;

    float acc[8];
    {
        float4 raw = h4[(size_t)node * 8 + c];   // self loop (pre-scaled)
        __half2* hp = (__half2*)&raw;
#pragma unroll
        for (int q = 0; q < 4; q++) {
            float2 f = __half22float2(hp[q]);
            acc[2 * q + 0] = f.x;
            acc[2 * q + 1] = f.y;
        }
    }

    int e0 = g_rowstart[node];
    int e1 = g_rowstart[node + 1];
    int e = e0;
    for (; e + 3 < e1; e += 4) {
        int s0 = g_csrc[e];
        int s1 = g_csrc[e + 1];
        int s2 = g_csrc[e + 2];
        int s3 = g_csrc[e + 3];
        float4 r0 = h4[(size_t)s0 * 8 + c];
        float4 r1 = h4[(size_t)s1 * 8 + c];
        float4 r2 = h4[(size_t)s2 * 8 + c];
        float4 r3 = h4[(size_t)s3 * 8 + c];
        __half2* p0 = (__half2*)&r0;
        __half2* p1 = (__half2*)&r1;
        __half2* p2 = (__half2*)&r2;
        __half2* p3 = (__half2*)&r3;
#pragma unroll
        for (int q = 0; q < 4; q++) {
            __half2 a01 = __hadd2(p0[q], p1[q]);
            __half2 a23 = __hadd2(p2[q], p3[q]);
            __half2 s4h = __hadd2(a01, a23);
            float2 f = __half22float2(s4h);
            acc[2 * q + 0] += f.x;
            acc[2 * q + 1] += f.y;
        }
    }
    for (; e < e1; e++) {
        float4 r = h4[(size_t)g_csrc[e] * 8 + c];
        __half2* hp = (__half2*)&r;
#pragma unroll
        for (int q = 0; q < 4; q++) {
            float2 f = __half22float2(hp[q]);
            acc[2 * q + 0] += f.x;
            acc[2 * q + 1] += f.y;
        }
    }

    float di = g_dinv[node];
    float o[8];
    const float4* bb = (const float4*)(b + c * 8);
    float4 b0 = bb[0], b1 = bb[1];
    o[0] = fmaxf(acc[0] * di + b0.x, 0.f);
    o[1] = fmaxf(acc[1] * di + b0.y, 0.f);
    o[2] = fmaxf(acc[2] * di + b0.z, 0.f);
    o[3] = fmaxf(acc[3] * di + b0.w, 0.f);
    o[4] = fmaxf(acc[4] * di + b1.x, 0.f);
    o[5] = fmaxf(acc[5] * di + b1.y, 0.f);
    o[6] = fmaxf(acc[6] * di + b1.z, 0.f);
    o[7] = fmaxf(acc[7] * di + b1.w, 0.f);

    if (FUSE_POOL) {
        int lane = threadIdx.x & 31;
        unsigned gmask = 0xffu << (lane & 24);
        const float4* ww = (const float4*)(fcw + c * 8);
        float4 w0 = ww[0], w1 = ww[1];
        float dot = o[0] * w0.x + o[1] * w0.y + o[2] * w0.z + o[3] * w0.w
                  + o[4] * w1.x + o[5] * w1.y + o[6] * w1.z + o[7] * w1.w;
#pragma unroll
        for (int off = 4; off > 0; off >>= 1)
            dot += __shfl_down_sync(gmask, dot, off, 8);
        if (c == 0) g_nodedot[node] = dot;
    } else {
        __half2 p0 = __floats2half2_rn(o[0], o[1]);
        __half2 p1 = __floats2half2_rn(o[2], o[3]);
        __half2 p2 = __floats2half2_rn(o[4], o[5]);
        __half2 p3 = __floats2half2_rn(o[6], o[7]);
        uint4 u;
        u.x = *(unsigned*)&p0; u.y = *(unsigned*)&p1;
        u.z = *(unsigned*)&p2; u.w = *(unsigned*)&p3;
        ((uint4*)out)[(size_t)node * 8 + c] = u;
    }
}

// ------- pool + head: one block per graph over per-node scalars --------------
__global__ void __launch_bounds__(256) k_pool_graph(const float* __restrict__ fcb,
                                                    const int* __restrict__ batch,
                                                    float* __restrict__ out) {
    __shared__ int bounds[2];
    __shared__ float red[256 / 32];
    int tid = threadIdx.x;
    int g = blockIdx.x;
    if (tid == 0 || tid == 1) {
        int key = g + tid;
        int lo = 0, hi = N_NODES;
        while (lo < hi) {
            int mid = (lo + hi) >> 1;
            if (batch[mid] < key) lo = mid + 1; else hi = mid;
        }
        bounds[tid] = lo;
    }
    __syncthreads();
    int start = bounds[0], end = bounds[1];

    float s = 0.f;
    for (int i = start + tid; i < end; i += 256) s += g_nodedot[i];
#pragma unroll
    for (int off = 16; off > 0; off >>= 1)
        s += __shfl_down_sync(0xffffffffu, s, off);
    if ((tid & 31) == 0) red[tid >> 5] = s;
    __syncthreads();
    if (tid == 0) {
        float tot = 0.f;
#pragma unroll
        for (int wi = 0; wi < 256 / 32; wi++) tot += red[wi];
        int cnt = end - start;
        out[g] = tot / fmaxf((float)cnt, 1.f) + fcb[0];
    }
}

// ---------------- launch ------------------------------------------------------
extern "C" void kernel_launch(void* const* d_in, const int* in_sizes, int n_in,
                              void* d_out, int out_size) {
    const float* x     = (const float*)d_in[0];
    const int*   ei    = (const int*)  d_in[1];
    const int*   batch = (const int*)  d_in[2];
    const float* w0    = (const float*)d_in[3];
    const float* b0    = (const float*)d_in[4];
    const float* w1    = (const float*)d_in[5];
    const float* b1    = (const float*)d_in[6];
    const float* w2    = (const float*)d_in[7];
    const float* b2    = (const float*)d_in[8];
    const float* fcw   = (const float*)d_in[9];
    const float* fcb   = (const float*)d_in[10];
    float* out = (float*)d_out;

    __half *h, *t0, *t1;
    void *p_dege;
    cudaGetSymbolAddress((void**)&h,  g_h);
    cudaGetSymbolAddress((void**)&t0, g_t0);
    cudaGetSymbolAddress((void**)&t1, g_t1);
    cudaGetSymbolAddress(&p_dege, g_dege);

    // lazily-created side stream + fork/join events (host objects only; the
    // captured graph is identical on every call)
    static cudaStream_t s2 = nullptr;
    static cudaEvent_t evFork = nullptr, evJoin = nullptr;
    if (!s2) {
        cudaStreamCreateWithFlags(&s2, cudaStreamNonBlocking);
        cudaEventCreateWithFlags(&evFork, cudaEventDisableTiming);
        cudaEventCreateWithFlags(&evJoin, cudaEventDisableTiming);
    }

    const int TB = 256;
    int nb_nodes  = (N_NODES + TB - 1) / TB;           // 391
    int nb_edge4  = (N_EDGES / 4 + TB - 1) / TB;       // 1250
    int nb_gemm   = (N_NODES + 127) / 128;             // 782
    int nb_gath   = (N_NODES * 8) / TB;                // 3125 exact

    cudaMemsetAsync(p_dege, 0, (N_NODES + 1) * sizeof(int));

    // degrees, then dinv (the only CSR product GEMM1 needs)
    k_deg <<<nb_edge4, TB>>>(ei);
    k_dinv<<<nb_nodes, TB>>>();

    // fork: GEMM1 overlaps with the whole scan+fill phase
    cudaEventRecord(evFork, 0);
    cudaStreamWaitEvent(s2, evFork, 0);
    k_gemm_f32<<<nb_gemm, 256, 0, s2>>>(x, w0, h);
    cudaEventRecord(evJoin, s2);

    // rest of CSR build on main stream (concurrent with GEMM1)
    k_scan1<<<N_SCANBLK, SCAN_B>>>();     // includes last-block tile-sum scan
    k_scan3<<<nb_nodes, TB>>>();
    k_fill <<<nb_edge4, TB>>>(ei);

    // join: gather1 needs both csrc and GEMM1 output
    cudaStreamWaitEvent(0, evJoin, 0);

    // layer 1 gather
    k_gather8<false><<<nb_gath, TB>>>(h, b0, t0, nullptr);
    // layer 2
    k_gemm_f16<<<nb_gemm, 256>>>(t0, w1, h);
    k_gather8<false><<<nb_gath, TB>>>(h, b1, t1, nullptr);
    // layer 3 (gather fused with pool dot)
    k_gemm_f16<<<nb_gemm, 256>>>(t1, w2, h);
    k_gather8<true><<<nb_gath, TB>>>(h, b2, nullptr, fcw);

    // pool + head
    k_pool_graph<<<N_GRAPHS, 256>>>(fcb, batch, out);
}

// round 16
// speedup vs baseline: 1.1133x; 1.1133x over previous
#include <cuda_runtime.h>
#include <cuda_fp16.h>
#include <mma.h>
using namespace nvcuda;

#define N_NODES   100000
#define N_EDGES   1280000
#define D         64
#define N_GRAPHS  512
#define SCAN_B    1024
#define N_SCANBLK ((N_NODES + SCAN_B - 1) / SCAN_B)   // 98
#define LDW       72

// ---------------- scratch (device globals; no cudaMalloc allowed) -----------
__device__ __half g_h  [N_NODES * D];   // GEMM output, pre-scaled by dinv[row]
__device__ __half g_t0 [N_NODES * D];
__device__ __half g_t1 [N_NODES * D];
__device__ float  g_dinv[N_NODES];
__device__ int    g_dege[N_NODES + 1]; // [N_NODES] = last-block counter
__device__ int    g_rowstart[N_NODES + 1];
__device__ int    g_bsums[128];
__device__ int    g_csrc [N_EDGES];
__device__ int    g_rank [N_EDGES];
__device__ float  g_nodedot[N_NODES];

// ---------------- setup kernels ---------------------------------------------
__global__ void k_deg(const int* __restrict__ ei) {
    int t = blockIdx.x * blockDim.x + threadIdx.x;
    if (t < N_EDGES / 4) {
        int4 d4 = ((const int4*)(ei + N_EDGES))[t];
        int4 r;
        r.x = atomicAdd(&g_dege[d4.x], 1);
        r.y = atomicAdd(&g_dege[d4.y], 1);
        r.z = atomicAdd(&g_dege[d4.z], 1);
        r.w = atomicAdd(&g_dege[d4.w], 1);
        ((int4*)g_rank)[t] = r;
    }
}

// per-tile scan + last-block scans the tile sums
__global__ void __launch_bounds__(1024) k_scan1() {
    __shared__ int sh[SCAN_B];
    __shared__ bool amLast;
    int tid = threadIdx.x;
    int i = blockIdx.x * SCAN_B + tid;
    int v = (i < N_NODES) ? g_dege[i] : 0;
    sh[tid] = v;
    __syncthreads();
    for (int off = 1; off < SCAN_B; off <<= 1) {
        int t = 0;
        if (tid >= off) t = sh[tid - off];
        __syncthreads();
        sh[tid] += t;
        __syncthreads();
    }
    int incl = sh[tid];
    if (i < N_NODES) g_rowstart[i] = incl - v;   // exclusive within tile
    if (tid == SCAN_B - 1) g_bsums[blockIdx.x] = incl;

    __threadfence();
    if (tid == 0) {
        int prev = atomicAdd(&g_dege[N_NODES], 1);
        amLast = (prev == (int)gridDim.x - 1);
    }
    __syncthreads();
    if (amLast) {
        int v2 = (tid < N_SCANBLK) ? g_bsums[tid] : 0;
        if (tid < 128) sh[tid] = v2;
        __syncthreads();
        for (int off = 1; off < 128; off <<= 1) {
            int t = (tid >= off && tid < 128) ? sh[tid - off] : 0;
            __syncthreads();
            if (tid < 128) sh[tid] += t;
            __syncthreads();
        }
        if (tid < N_SCANBLK) g_bsums[tid] = sh[tid] - v2;   // exclusive
        if (tid == N_SCANBLK - 1) g_rowstart[N_NODES] = sh[tid];
    }
}

__global__ void k_scan3() {
    int i = blockIdx.x * blockDim.x + threadIdx.x;
    if (i < N_NODES) {
        g_rowstart[i] = g_rowstart[i] + g_bsums[i / SCAN_B];
        g_dinv[i] = rsqrtf((float)(g_dege[i] + 1));   // +1 self loop
    }
}

__global__ void k_fill(const int* __restrict__ ei) {
    int t = blockIdx.x * blockDim.x + threadIdx.x;
    if (t < N_EDGES / 4) {
        int4 s4 = ((const int4*)ei)[t];
        int4 d4 = ((const int4*)(ei + N_EDGES))[t];
        int4 r4 = ((const int4*)g_rank)[t];
        g_csrc[g_rowstart[d4.x] + r4.x] = s4.x;
        g_csrc[g_rowstart[d4.y] + r4.y] = s4.y;
        g_csrc[g_rowstart[d4.z] + r4.z] = s4.z;
        g_csrc[g_rowstart[d4.w] + r4.w] = s4.w;
    }
}

// ---------------- fp32 -> 2x half2 pack helper --------------------------------
__device__ __forceinline__ uint2 pack_f4_h4(float4 v) {
    __half2 lo = __floats2half2_rn(v.x, v.y);
    __half2 hi = __floats2half2_rn(v.z, v.w);
    uint2 u;
    u.x = *(unsigned*)&lo;
    u.y = *(unsigned*)&hi;
    return u;
}

// vectorized weight load: 64x64 fp32 -> fp16 smem (LDW stride), float4 granular
template <int NT>
__device__ __forceinline__ void load_weights_vec(__half* wsh, const float* __restrict__ W, int tid) {
    for (int i4 = tid; i4 < (D * D) / 4; i4 += NT) {
        int lin = i4 * 4;
        int r = lin >> 6, c = lin & 63;
        float4 v = ((const float4*)W)[i4];
        *(uint2*)(wsh + r * LDW + c) = pack_f4_h4(v);
    }
}

// ---------------- tensor-core GEMM: out[row] = dinv[row]*(in[row] @ W), fp16 out
__device__ __forceinline__ void gemm_epilogue128(const float* osh, __half* __restrict__ out,
                                                 int blockRow0, int tid) {
    int r = tid >> 1;                 // 0..127
    int cbase = (tid & 1) * 32;
    int row = blockRow0 + r;
    if (row >= N_NODES) return;
    float s = g_dinv[row];
    uint4* orow = (uint4*)(out + (size_t)row * D + cbase);
    const float* src = osh + r * LDW + cbase;
#pragma unroll
    for (int q = 0; q < 4; q++) {
        __half2 p0 = __floats2half2_rn(src[q * 8 + 0] * s, src[q * 8 + 1] * s);
        __half2 p1 = __floats2half2_rn(src[q * 8 + 2] * s, src[q * 8 + 3] * s);
        __half2 p2 = __floats2half2_rn(src[q * 8 + 4] * s, src[q * 8 + 5] * s);
        __half2 p3 = __floats2half2_rn(src[q * 8 + 6] * s, src[q * 8 + 7] * s);
        uint4 u;
        u.x = *(unsigned*)&p0; u.y = *(unsigned*)&p1;
        u.z = *(unsigned*)&p2; u.w = *(unsigned*)&p3;
        orow[q] = u;
    }
}

__global__ void __launch_bounds__(256) k_gemm_f16(const __half* __restrict__ in,
                                                  const float* __restrict__ W,
                                                  __half* __restrict__ out) {
    __shared__ __half wsh[D * LDW];
    __shared__ float  osh[128 * LDW];
    int tid = threadIdx.x;
    load_weights_vec<256>(wsh, W, tid);
    __syncthreads();

    int warp = tid >> 5;
    int row0 = blockIdx.x * 128 + warp * 16;
    if (row0 < N_NODES) {
        wmma::fragment<wmma::accumulator, 16, 16, 16, float> acc[4];
#pragma unroll
        for (int n = 0; n < 4; n++) wmma::fill_fragment(acc[n], 0.0f);
#pragma unroll
        for (int k = 0; k < 4; k++) {
            wmma::fragment<wmma::matrix_a, 16, 16, 16, __half, wmma::row_major> a;
            wmma::load_matrix_sync(a, in + (size_t)row0 * D + k * 16, D);
#pragma unroll
            for (int n = 0; n < 4; n++) {
                wmma::fragment<wmma::matrix_b, 16, 16, 16, __half, wmma::row_major> b;
                wmma::load_matrix_sync(b, wsh + (k * 16) * LDW + n * 16, LDW);
                wmma::mma_sync(acc[n], a, b, acc[n]);
            }
        }
#pragma unroll
        for (int n = 0; n < 4; n++)
            wmma::store_matrix_sync(osh + (warp * 16) * LDW + n * 16, acc[n], LDW, wmma::mem_row_major);
    }
    __syncthreads();
    gemm_epilogue128(osh, out, blockIdx.x * 128, tid);
}

// fp32-input GEMM (layer 1): 256 threads / 128 rows; VECTORIZED staging
// (float4 loads, 8-byte half stores); fp16 staging buffer OVERLAYED on the
// fp32 output buffer (accumulators bridge the switch).
__global__ void __launch_bounds__(256) k_gemm_f32(const float* __restrict__ in,
                                                  const float* __restrict__ W,
                                                  __half* __restrict__ out) {
    __shared__ __half wsh[D * LDW];
    __shared__ float  osh[128 * LDW];
    __half* ash = (__half*)osh;
    int tid = threadIdx.x;

    load_weights_vec<256>(wsh, W, tid);

    // stage 128 rows of x: 2048 float4 total, 8 per thread
    int blockRow0 = blockIdx.x * 128;
#pragma unroll
    for (int it = 0; it < 8; it++) {
        int i4 = tid + it * 256;
        int lin = i4 * 4;
        int r = lin >> 6, c = lin & 63;
        int row = blockRow0 + r;
        float4 v = (row < N_NODES) ? ((const float4*)(in + (size_t)row * D))[c >> 2]
                                   : make_float4(0.f, 0.f, 0.f, 0.f);
        *(uint2*)(ash + r * LDW + c) = pack_f4_h4(v);
    }
    __syncthreads();

    int warp = tid >> 5;
    int row0 = blockRow0 + warp * 16;
    wmma::fragment<wmma::accumulator, 16, 16, 16, float> acc[4];
    if (row0 < N_NODES) {
#pragma unroll
        for (int n = 0; n < 4; n++) wmma::fill_fragment(acc[n], 0.0f);
#pragma unroll
        for (int k = 0; k < 4; k++) {
            wmma::fragment<wmma::matrix_a, 16, 16, 16, __half, wmma::row_major> a;
            wmma::load_matrix_sync(a, ash + (warp * 16) * LDW + k * 16, LDW);
#pragma unroll
            for (int n = 0; n < 4; n++) {
                wmma::fragment<wmma::matrix_b, 16, 16, 16, __half, wmma::row_major> b;
                wmma::load_matrix_sync(b, wsh + (k * 16) * LDW + n * 16, LDW);
                wmma::mma_sync(acc[n], a, b, acc[n]);
            }
        }
    }
    __syncthreads();   // all warps done reading ash before osh overwrites it
    if (row0 < N_NODES) {
#pragma unroll
        for (int n = 0; n < 4; n++)
            wmma::store_matrix_sync(osh + (warp * 16) * LDW + n * 16, acc[n], LDW, wmma::mem_row_major);
    }
    __syncthreads();
    gemm_epilogue128(osh, out, blockRow0, tid);
}

// ------- gather: 8 lanes/node, LDG.128 per edge, half2-tree accumulate -------
template <bool FUSE_POOL>
__global__ void __launch_bounds__(256) k_gather8(const __half* __restrict__ h,
                                                 const float* __restrict__ b,
                                                 __half* __restrict__ out,
                                                 const float* __restrict__ fcw) {
    int gt = blockIdx.x * blockDim.x + threadIdx.x;
    int node = gt >> 3;
    int c = gt & 7;

    const float4* h4 = (const float4*)h;

    float acc[8];
    {
        float4 raw = h4[(size_t)node * 8 + c];   // self loop (pre-scaled)
        __half2* hp = (__half2*)&raw;
#pragma unroll
        for (int q = 0; q < 4; q++) {
            float2 f = __half22float2(hp[q]);
            acc[2 * q + 0] = f.x;
            acc[2 * q + 1] = f.y;
        }
    }

    int e0 = g_rowstart[node];
    int e1 = g_rowstart[node + 1];
    int e = e0;
    for (; e + 3 < e1; e += 4) {
        int s0 = g_csrc[e];
        int s1 = g_csrc[e + 1];
        int s2 = g_csrc[e + 2];
        int s3 = g_csrc[e + 3];
        float4 r0 = h4[(size_t)s0 * 8 + c];
        float4 r1 = h4[(size_t)s1 * 8 + c];
        float4 r2 = h4[(size_t)s2 * 8 + c];
        float4 r3 = h4[(size_t)s3 * 8 + c];
        __half2* p0 = (__half2*)&r0;
        __half2* p1 = (__half2*)&r1;
        __half2* p2 = (__half2*)&r2;
        __half2* p3 = (__half2*)&r3;
#pragma unroll
        for (int q = 0; q < 4; q++) {
            __half2 a01 = __hadd2(p0[q], p1[q]);
            __half2 a23 = __hadd2(p2[q], p3[q]);
            __half2 s4h = __hadd2(a01, a23);
            float2 f = __half22float2(s4h);
            acc[2 * q + 0] += f.x;
            acc[2 * q + 1] += f.y;
        }
    }
    for (; e < e1; e++) {
        float4 r = h4[(size_t)g_csrc[e] * 8 + c];
        __half2* hp = (__half2*)&r;
#pragma unroll
        for (int q = 0; q < 4; q++) {
            float2 f = __half22float2(hp[q]);
            acc[2 * q + 0] += f.x;
            acc[2 * q + 1] += f.y;
        }
    }

    float di = g_dinv[node];
    float o[8];
    const float4* bb = (const float4*)(b + c * 8);
    float4 b0 = bb[0], b1 = bb[1];
    o[0] = fmaxf(acc[0] * di + b0.x, 0.f);
    o[1] = fmaxf(acc[1] * di + b0.y, 0.f);
    o[2] = fmaxf(acc[2] * di + b0.z, 0.f);
    o[3] = fmaxf(acc[3] * di + b0.w, 0.f);
    o[4] = fmaxf(acc[4] * di + b1.x, 0.f);
    o[5] = fmaxf(acc[5] * di + b1.y, 0.f);
    o[6] = fmaxf(acc[6] * di + b1.z, 0.f);
    o[7] = fmaxf(acc[7] * di + b1.w, 0.f);

    if (FUSE_POOL) {
        int lane = threadIdx.x & 31;
        unsigned gmask = 0xffu << (lane & 24);
        const float4* ww = (const float4*)(fcw + c * 8);
        float4 w0 = ww[0], w1 = ww[1];
        float dot = o[0] * w0.x + o[1] * w0.y + o[2] * w0.z + o[3] * w0.w
                  + o[4] * w1.x + o[5] * w1.y + o[6] * w1.z + o[7] * w1.w;
#pragma unroll
        for (int off = 4; off > 0; off >>= 1)
            dot += __shfl_down_sync(gmask, dot, off, 8);
        if (c == 0) g_nodedot[node] = dot;
    } else {
        __half2 p0 = __floats2half2_rn(o[0], o[1]);
        __half2 p1 = __floats2half2_rn(o[2], o[3]);
        __half2 p2 = __floats2half2_rn(o[4], o[5]);
        __half2 p3 = __floats2half2_rn(o[6], o[7]);
        uint4 u;
        u.x = *(unsigned*)&p0; u.y = *(unsigned*)&p1;
        u.z = *(unsigned*)&p2; u.w = *(unsigned*)&p3;
        ((uint4*)out)[(size_t)node * 8 + c] = u;
    }
}

// ------- pool + head: one block per graph over per-node scalars --------------
__global__ void __launch_bounds__(256) k_pool_graph(const float* __restrict__ fcb,
                                                    const int* __restrict__ batch,
                                                    float* __restrict__ out) {
    __shared__ int bounds[2];
    __shared__ float red[256 / 32];
    int tid = threadIdx.x;
    int g = blockIdx.x;
    if (tid == 0 || tid == 1) {
        int key = g + tid;
        int lo = 0, hi = N_NODES;
        while (lo < hi) {
            int mid = (lo + hi) >> 1;
            if (batch[mid] < key) lo = mid + 1; else hi = mid;
        }
        bounds[tid] = lo;
    }
    __syncthreads();
    int start = bounds[0], end = bounds[1];

    float s = 0.f;
    for (int i = start + tid; i < end; i += 256) s += g_nodedot[i];
#pragma unroll
    for (int off = 16; off > 0; off >>= 1)
        s += __shfl_down_sync(0xffffffffu, s, off);
    if ((tid & 31) == 0) red[tid >> 5] = s;
    __syncthreads();
    if (tid == 0) {
        float tot = 0.f;
#pragma unroll
        for (int wi = 0; wi < 256 / 32; wi++) tot += red[wi];
        int cnt = end - start;
        out[g] = tot / fmaxf((float)cnt, 1.f) + fcb[0];
    }
}

// ---------------- launch ------------------------------------------------------
extern "C" void kernel_launch(void* const* d_in, const int* in_sizes, int n_in,
                              void* d_out, int out_size) {
    const float* x     = (const float*)d_in[0];
    const int*   ei    = (const int*)  d_in[1];
    const int*   batch = (const int*)  d_in[2];
    const float* w0    = (const float*)d_in[3];
    const float* b0    = (const float*)d_in[4];
    const float* w1    = (const float*)d_in[5];
    const float* b1    = (const float*)d_in[6];
    const float* w2    = (const float*)d_in[7];
    const float* b2    = (const float*)d_in[8];
    const float* fcw   = (const float*)d_in[9];
    const float* fcb   = (const float*)d_in[10];
    float* out = (float*)d_out;

    __half *h, *t0, *t1;
    void *p_dege;
    cudaGetSymbolAddress((void**)&h,  g_h);
    cudaGetSymbolAddress((void**)&t0, g_t0);
    cudaGetSymbolAddress((void**)&t1, g_t1);
    cudaGetSymbolAddress(&p_dege, g_dege);

    const int TB = 256;
    int nb_nodes  = (N_NODES + TB - 1) / TB;           // 391
    int nb_edge4  = (N_EDGES / 4 + TB - 1) / TB;       // 1250
    int nb_gemm   = (N_NODES + 127) / 128;             // 782
    int nb_gath   = (N_NODES * 8) / TB;                // 3125 exact

    cudaMemsetAsync(p_dege, 0, (N_NODES + 1) * sizeof(int));

    // CSR build (once per call, reused by all 3 layers)
    k_deg  <<<nb_edge4, TB>>>(ei);
    k_scan1<<<N_SCANBLK, SCAN_B>>>();     // includes last-block tile-sum scan
    k_scan3<<<nb_nodes, TB>>>();
    k_fill <<<nb_edge4, TB>>>(ei);

    // layer 1
    k_gemm_f32<<<nb_gemm, 256>>>(x, w0, h);
    k_gather8<false><<<nb_gath, TB>>>(h, b0, t0, nullptr);
    // layer 2
    k_gemm_f16<<<nb_gemm, 256>>>(t0, w1, h);
    k_gather8<false><<<nb_gath, TB>>>(h, b1, t1, nullptr);
    // layer 3 (gather fused with pool dot)
    k_gemm_f16<<<nb_gemm, 256>>>(t1, w2, h);
    k_gather8<true><<<nb_gath, TB>>>(h, b2, nullptr, fcw);

    // pool + head
    k_pool_graph<<<N_GRAPHS, 256>>>(fcb, batch, out);
}

// round 17
// speedup vs baseline: 1.1165x; 1.0029x over previous
#include <cuda_runtime.h>
#include <cuda_fp16.h>
#include <mma.h>
using namespace nvcuda;

#define N_NODES   100000
#define N_EDGES   1280000
#define D         64
#define N_GRAPHS  512
#define SCAN_B    1024
#define N_SCANBLK ((N_NODES + SCAN_B - 1) / SCAN_B)   // 98
#define LDW       72

// ---------------- scratch (device globals; no cudaMalloc allowed) -----------
__device__ __half g_h  [N_NODES * D];   // GEMM output, pre-scaled by dinv[row]
__device__ __half g_t0 [N_NODES * D];
__device__ __half g_t1 [N_NODES * D];
__device__ float  g_dinv[N_NODES];
__device__ int    g_dege[N_NODES + 1]; // [N_NODES] = last-block counter
__device__ int    g_rowstart[N_NODES + 1];   // TILE-LOCAL exclusive prefix
__device__ int    g_bsums[128];              // exclusive tile offsets
__device__ int    g_csrc [N_EDGES];
__device__ int    g_rank [N_EDGES];
__device__ float  g_nodedot[N_NODES];

// ---------------- setup kernels ---------------------------------------------
__global__ void k_deg(const int* __restrict__ ei) {
    int t = blockIdx.x * blockDim.x + threadIdx.x;
    if (t < N_EDGES / 4) {
        int4 d4 = ((const int4*)(ei + N_EDGES))[t];
        int4 r;
        r.x = atomicAdd(&g_dege[d4.x], 1);
        r.y = atomicAdd(&g_dege[d4.y], 1);
        r.z = atomicAdd(&g_dege[d4.z], 1);
        r.w = atomicAdd(&g_dege[d4.w], 1);
        ((int4*)g_rank)[t] = r;
    }
}

// per-tile scan (tile-local rowstart) + dinv + last-block scans the tile sums.
// rowstart stays TILE-LOCAL; consumers add g_bsums[i>>10].
__global__ void __launch_bounds__(1024) k_scan1() {
    __shared__ int sh[SCAN_B];
    __shared__ bool amLast;
    int tid = threadIdx.x;
    int i = blockIdx.x * SCAN_B + tid;
    int v = (i < N_NODES) ? g_dege[i] : 0;
    if (i < N_NODES) g_dinv[i] = rsqrtf((float)(v + 1));   // +1 self loop
    sh[tid] = v;
    __syncthreads();
    for (int off = 1; off < SCAN_B; off <<= 1) {
        int t = 0;
        if (tid >= off) t = sh[tid - off];
        __syncthreads();
        sh[tid] += t;
        __syncthreads();
    }
    int incl = sh[tid];
    if (i <= N_NODES) g_rowstart[i] = incl - v;   // tile-local exclusive
    if (tid == SCAN_B - 1) g_bsums[blockIdx.x] = incl;

    __threadfence();
    if (tid == 0) {
        int prev = atomicAdd(&g_dege[N_NODES], 1);
        amLast = (prev == (int)gridDim.x - 1);
    }
    __syncthreads();
    if (amLast) {
        int v2 = (tid < N_SCANBLK) ? g_bsums[tid] : 0;
        if (tid < 128) sh[tid] = v2;
        __syncthreads();
        for (int off = 1; off < 128; off <<= 1) {
            int t = (tid >= off && tid < 128) ? sh[tid - off] : 0;
            __syncthreads();
            if (tid < 128) sh[tid] += t;
            __syncthreads();
        }
        if (tid < N_SCANBLK) g_bsums[tid] = sh[tid] - v2;   // exclusive
    }
}

// fill: absolute position = local rowstart + tile offset + rank
__global__ void k_fill(const int* __restrict__ ei) {
    int t = blockIdx.x * blockDim.x + threadIdx.x;
    if (t < N_EDGES / 4) {
        int4 s4 = ((const int4*)ei)[t];
        int4 d4 = ((const int4*)(ei + N_EDGES))[t];
        int4 r4 = ((const int4*)g_rank)[t];
        g_csrc[g_rowstart[d4.x] + g_bsums[d4.x >> 10] + r4.x] = s4.x;
        g_csrc[g_rowstart[d4.y] + g_bsums[d4.y >> 10] + r4.y] = s4.y;
        g_csrc[g_rowstart[d4.z] + g_bsums[d4.z >> 10] + r4.z] = s4.z;
        g_csrc[g_rowstart[d4.w] + g_bsums[d4.w >> 10] + r4.w] = s4.w;
    }
}

// ---------------- fp32 -> 2x half2 pack helper --------------------------------
__device__ __forceinline__ uint2 pack_f4_h4(float4 v) {
    __half2 lo = __floats2half2_rn(v.x, v.y);
    __half2 hi = __floats2half2_rn(v.z, v.w);
    uint2 u;
    u.x = *(unsigned*)&lo;
    u.y = *(unsigned*)&hi;
    return u;
}

template <int NT>
__device__ __forceinline__ void load_weights_vec(__half* wsh, const float* __restrict__ W, int tid) {
    for (int i4 = tid; i4 < (D * D) / 4; i4 += NT) {
        int lin = i4 * 4;
        int r = lin >> 6, c = lin & 63;
        float4 v = ((const float4*)W)[i4];
        *(uint2*)(wsh + r * LDW + c) = pack_f4_h4(v);
    }
}

// ---------------- tensor-core GEMM: out[row] = dinv[row]*(in[row] @ W), fp16 out
__device__ __forceinline__ void gemm_epilogue128(const float* osh, __half* __restrict__ out,
                                                 int blockRow0, int tid) {
    int r = tid >> 1;                 // 0..127
    int cbase = (tid & 1) * 32;
    int row = blockRow0 + r;
    if (row >= N_NODES) return;
    float s = g_dinv[row];
    uint4* orow = (uint4*)(out + (size_t)row * D + cbase);
    const float* src = osh + r * LDW + cbase;
#pragma unroll
    for (int q = 0; q < 4; q++) {
        __half2 p0 = __floats2half2_rn(src[q * 8 + 0] * s, src[q * 8 + 1] * s);
        __half2 p1 = __floats2half2_rn(src[q * 8 + 2] * s, src[q * 8 + 3] * s);
        __half2 p2 = __floats2half2_rn(src[q * 8 + 4] * s, src[q * 8 + 5] * s);
        __half2 p3 = __floats2half2_rn(src[q * 8 + 6] * s, src[q * 8 + 7] * s);
        uint4 u;
        u.x = *(unsigned*)&p0; u.y = *(unsigned*)&p1;
        u.z = *(unsigned*)&p2; u.w = *(unsigned*)&p3;
        orow[q] = u;
    }
}

__global__ void __launch_bounds__(256) k_gemm_f16(const __half* __restrict__ in,
                                                  const float* __restrict__ W,
                                                  __half* __restrict__ out) {
    __shared__ __half wsh[D * LDW];
    __shared__ float  osh[128 * LDW];
    int tid = threadIdx.x;
    load_weights_vec<256>(wsh, W, tid);
    __syncthreads();

    int warp = tid >> 5;
    int row0 = blockIdx.x * 128 + warp * 16;
    if (row0 < N_NODES) {
        wmma::fragment<wmma::accumulator, 16, 16, 16, float> acc[4];
#pragma unroll
        for (int n = 0; n < 4; n++) wmma::fill_fragment(acc[n], 0.0f);
#pragma unroll
        for (int k = 0; k < 4; k++) {
            wmma::fragment<wmma::matrix_a, 16, 16, 16, __half, wmma::row_major> a;
            wmma::load_matrix_sync(a, in + (size_t)row0 * D + k * 16, D);
#pragma unroll
            for (int n = 0; n < 4; n++) {
                wmma::fragment<wmma::matrix_b, 16, 16, 16, __half, wmma::row_major> b;
                wmma::load_matrix_sync(b, wsh + (k * 16) * LDW + n * 16, LDW);
                wmma::mma_sync(acc[n], a, b, acc[n]);
            }
        }
#pragma unroll
        for (int n = 0; n < 4; n++)
            wmma::store_matrix_sync(osh + (warp * 16) * LDW + n * 16, acc[n], LDW, wmma::mem_row_major);
    }
    __syncthreads();
    gemm_epilogue128(osh, out, blockIdx.x * 128, tid);
}

// fp32-input GEMM (layer 1): vectorized staging; ash overlayed on osh.
__global__ void __launch_bounds__(256) k_gemm_f32(const float* __restrict__ in,
                                                  const float* __restrict__ W,
                                                  __half* __restrict__ out) {
    __shared__ __half wsh[D * LDW];
    __shared__ float  osh[128 * LDW];
    __half* ash = (__half*)osh;
    int tid = threadIdx.x;

    load_weights_vec<256>(wsh, W, tid);

    int blockRow0 = blockIdx.x * 128;
#pragma unroll
    for (int it = 0; it < 8; it++) {
        int i4 = tid + it * 256;
        int lin = i4 * 4;
        int r = lin >> 6, c = lin & 63;
        int row = blockRow0 + r;
        float4 v = (row < N_NODES) ? ((const float4*)(in + (size_t)row * D))[c >> 2]
                                   : make_float4(0.f, 0.f, 0.f, 0.f);
        *(uint2*)(ash + r * LDW + c) = pack_f4_h4(v);
    }
    __syncthreads();

    int warp = tid >> 5;
    int row0 = blockRow0 + warp * 16;
    wmma::fragment<wmma::accumulator, 16, 16, 16, float> acc[4];
    if (row0 < N_NODES) {
#pragma unroll
        for (int n = 0; n < 4; n++) wmma::fill_fragment(acc[n], 0.0f);
#pragma unroll
        for (int k = 0; k < 4; k++) {
            wmma::fragment<wmma::matrix_a, 16, 16, 16, __half, wmma::row_major> a;
            wmma::load_matrix_sync(a, ash + (warp * 16) * LDW + k * 16, LDW);
#pragma unroll
            for (int n = 0; n < 4; n++) {
                wmma::fragment<wmma::matrix_b, 16, 16, 16, __half, wmma::row_major> b;
                wmma::load_matrix_sync(b, wsh + (k * 16) * LDW + n * 16, LDW);
                wmma::mma_sync(acc[n], a, b, acc[n]);
            }
        }
    }
    __syncthreads();   // all warps done reading ash before osh overwrites it
    if (row0 < N_NODES) {
#pragma unroll
        for (int n = 0; n < 4; n++)
            wmma::store_matrix_sync(osh + (warp * 16) * LDW + n * 16, acc[n], LDW, wmma::mem_row_major);
    }
    __syncthreads();
    gemm_epilogue128(osh, out, blockRow0, tid);
}

// ------- gather: 8 lanes/node, LDG.128 per edge, half2-tree accumulate -------
template <bool FUSE_POOL>
__global__ void __launch_bounds__(256) k_gather8(const __half* __restrict__ h,
                                                 const float* __restrict__ b,
                                                 __half* __restrict__ out,
                                                 const float* __restrict__ fcw) {
    int gt = blockIdx.x * blockDim.x + threadIdx.x;
    int node = gt >> 3;
    int c = gt & 7;

    const float4* h4 = (const float4*)h;

    float acc[8];
    {
        float4 raw = h4[(size_t)node * 8 + c];   // self loop (pre-scaled)
        __half2* hp = (__half2*)&raw;
#pragma unroll
        for (int q = 0; q < 4; q++) {
            float2 f = __half22float2(hp[q]);
            acc[2 * q + 0] = f.x;
            acc[2 * q + 1] = f.y;
        }
    }

    int e0 = g_rowstart[node]     + g_bsums[node >> 10];
    int e1 = g_rowstart[node + 1] + g_bsums[(node + 1) >> 10];
    int e = e0;
    for (; e + 3 < e1; e += 4) {
        int s0 = g_csrc[e];
        int s1 = g_csrc[e + 1];
        int s2 = g_csrc[e + 2];
        int s3 = g_csrc[e + 3];
        float4 r0 = h4[(size_t)s0 * 8 + c];
        float4 r1 = h4[(size_t)s1 * 8 + c];
        float4 r2 = h4[(size_t)s2 * 8 + c];
        float4 r3 = h4[(size_t)s3 * 8 + c];
        __half2* p0 = (__half2*)&r0;
        __half2* p1 = (__half2*)&r1;
        __half2* p2 = (__half2*)&r2;
        __half2* p3 = (__half2*)&r3;
#pragma unroll
        for (int q = 0; q < 4; q++) {
            __half2 a01 = __hadd2(p0[q], p1[q]);
            __half2 a23 = __hadd2(p2[q], p3[q]);
            __half2 s4h = __hadd2(a01, a23);
            float2 f = __half22float2(s4h);
            acc[2 * q + 0] += f.x;
            acc[2 * q + 1] += f.y;
        }
    }
    for (; e < e1; e++) {
        float4 r = h4[(size_t)g_csrc[e] * 8 + c];
        __half2* hp = (__half2*)&r;
#pragma unroll
        for (int q = 0; q < 4; q++) {
            float2 f = __half22float2(hp[q]);
            acc[2 * q + 0] += f.x;
            acc[2 * q + 1] += f.y;
        }
    }

    float di = g_dinv[node];
    float o[8];
    const float4* bb = (const float4*)(b + c * 8);
    float4 b0 = bb[0], b1 = bb[1];
    o[0] = fmaxf(acc[0] * di + b0.x, 0.f);
    o[1] = fmaxf(acc[1] * di + b0.y, 0.f);
    o[2] = fmaxf(acc[2] * di + b0.z, 0.f);
    o[3] = fmaxf(acc[3] * di + b0.w, 0.f);
    o[4] = fmaxf(acc[4] * di + b1.x, 0.f);
    o[5] = fmaxf(acc[5] * di + b1.y, 0.f);
    o[6] = fmaxf(acc[6] * di + b1.z, 0.f);
    o[7] = fmaxf(acc[7] * di + b1.w, 0.f);

    if (FUSE_POOL) {
        int lane = threadIdx.x & 31;
        unsigned gmask = 0xffu << (lane & 24);
        const float4* ww = (const float4*)(fcw + c * 8);
        float4 w0 = ww[0], w1 = ww[1];
        float dot = o[0] * w0.x + o[1] * w0.y + o[2] * w0.z + o[3] * w0.w
                  + o[4] * w1.x + o[5] * w1.y + o[6] * w1.z + o[7] * w1.w;
#pragma unroll
        for (int off = 4; off > 0; off >>= 1)
            dot += __shfl_down_sync(gmask, dot, off, 8);
        if (c == 0) g_nodedot[node] = dot;
    } else {
        __half2 p0 = __floats2half2_rn(o[0], o[1]);
        __half2 p1 = __floats2half2_rn(o[2], o[3]);
        __half2 p2 = __floats2half2_rn(o[4], o[5]);
        __half2 p3 = __floats2half2_rn(o[6], o[7]);
        uint4 u;
        u.x = *(unsigned*)&p0; u.y = *(unsigned*)&p1;
        u.z = *(unsigned*)&p2; u.w = *(unsigned*)&p3;
        ((uint4*)out)[(size_t)node * 8 + c] = u;
    }
}

// ------- pool + head: one block per graph over per-node scalars --------------
__global__ void __launch_bounds__(256) k_pool_graph(const float* __restrict__ fcb,
                                                    const int* __restrict__ batch,
                                                    float* __restrict__ out) {
    __shared__ int bounds[2];
    __shared__ float red[256 / 32];
    int tid = threadIdx.x;
    int g = blockIdx.x;
    if (tid == 0 || tid == 1) {
        int key = g + tid;
        int lo = 0, hi = N_NODES;
        while (lo < hi) {
            int mid = (lo + hi) >> 1;
            if (batch[mid] < key) lo = mid + 1; else hi = mid;
        }
        bounds[tid] = lo;
    }
    __syncthreads();
    int start = bounds[0], end = bounds[1];

    float s = 0.f;
    for (int i = start + tid; i < end; i += 256) s += g_nodedot[i];
#pragma unroll
    for (int off = 16; off > 0; off >>= 1)
        s += __shfl_down_sync(0xffffffffu, s, off);
    if ((tid & 31) == 0) red[tid >> 5] = s;
    __syncthreads();
    if (tid == 0) {
        float tot = 0.f;
#pragma unroll
        for (int wi = 0; wi < 256 / 32; wi++) tot += red[wi];
        int cnt = end - start;
        out[g] = tot / fmaxf((float)cnt, 1.f) + fcb[0];
    }
}

// ---------------- launch ------------------------------------------------------
extern "C" void kernel_launch(void* const* d_in, const int* in_sizes, int n_in,
                              void* d_out, int out_size) {
    const float* x     = (const float*)d_in[0];
    const int*   ei    = (const int*)  d_in[1];
    const int*   batch = (const int*)  d_in[2];
    const float* w0    = (const float*)d_in[3];
    const float* b0    = (const float*)d_in[4];
    const float* w1    = (const float*)d_in[5];
    const float* b1    = (const float*)d_in[6];
    const float* w2    = (const float*)d_in[7];
    const float* b2    = (const float*)d_in[8];
    const float* fcw   = (const float*)d_in[9];
    const float* fcb   = (const float*)d_in[10];
    float* out = (float*)d_out;

    __half *h, *t0, *t1;
    void *p_dege;
    cudaGetSymbolAddress((void**)&h,  g_h);
    cudaGetSymbolAddress((void**)&t0, g_t0);
    cudaGetSymbolAddress((void**)&t1, g_t1);
    cudaGetSymbolAddress(&p_dege, g_dege);

    static cudaStream_t s2 = nullptr;
    static cudaEvent_t evFork = nullptr, evJoin = nullptr;
    if (!s2) {
        cudaStreamCreateWithFlags(&s2, cudaStreamNonBlocking);
        cudaEventCreateWithFlags(&evFork, cudaEventDisableTiming);
        cudaEventCreateWithFlags(&evJoin, cudaEventDisableTiming);
    }

    const int TB = 256;
    int nb_edge4  = (N_EDGES / 4 + TB - 1) / TB;       // 1250
    int nb_gemm   = (N_NODES + 127) / 128;             // 782
    int nb_gath   = (N_NODES * 8) / TB;                // 3125 exact

    cudaMemsetAsync(p_dege, 0, (N_NODES + 1) * sizeof(int));

    // CSR build: deg -> scan1 (tile-local rowstart + bsums + dinv)
    k_deg  <<<nb_edge4, TB>>>(ei);
    k_scan1<<<N_SCANBLK, SCAN_B>>>();

    // fork: GEMM1 (needs only dinv) overlaps with k_fill (L2-queue bound)
    cudaEventRecord(evFork, 0);
    cudaStreamWaitEvent(s2, evFork, 0);
    k_gemm_f32<<<nb_gemm, 256, 0, s2>>>(x, w0, h);
    cudaEventRecord(evJoin, s2);

    k_fill <<<nb_edge4, TB>>>(ei);        // main stream, concurrent with GEMM1

    cudaStreamWaitEvent(0, evJoin, 0);

    // layer 1 gather
    k_gather8<false><<<nb_gath, TB>>>(h, b0, t0, nullptr);
    // layer 2
    k_gemm_f16<<<nb_gemm, 256>>>(t0, w1, h);
    k_gather8<false><<<nb_gath, TB>>>(h, b1, t1, nullptr);
    // layer 3 (gather fused with pool dot)
    k_gemm_f16<<<nb_gemm, 256>>>(t1, w2, h);
    k_gather8<true><<<nb_gath, TB>>>(h, b2, nullptr, fcw);

    // pool + head
    k_pool_graph<<<N_GRAPHS, 256>>>(fcb, batch, out);
}